// round 6
// baseline (speedup 1.0000x reference)
#include <cuda_runtime.h>
#include <cuda_bf16.h>
#include <cstdint>

// Fused edge-MLP CE loss via warp-level bf16 mma.sync.
// R6: explicit 2-stage ldmatrix fragment pipeline in the k-loop (prefetch ks+1
// during mma of ks) to hide LDS latency under the 124-reg/512-thread budget.

namespace {
constexpr int NHID    = 128;
constexpr int KDIM    = 256;
constexpr int TILE_E  = 128;
constexpr int THREADS = 512;
constexpr int A_BYTES = TILE_E * KDIM * 2;
constexpr int B_BYTES = KDIM * NHID * 2;
constexpr int DSMEM   = B_BYTES + 2 * A_BYTES + 256;
}

__device__ __align__(16) __nv_bfloat16 g_feat_bf16[(size_t)100000 * NHID];
__device__ __align__(16) __nv_bfloat16 g_w1_img[KDIM * NHID];
__device__ double g_loss_sum;

__device__ __forceinline__ uint32_t smem_u32(const void* p) {
    uint32_t a;
    asm("{ .reg .u64 t; cvta.to.shared.u64 t, %1; cvt.u32.u64 %0, t; }" : "=r"(a) : "l"(p));
    return a;
}

// ---------------- prep kernels ----------------
__global__ void hx_init_kernel() { g_loss_sum = 0.0; }

__global__ void hx_prep_feat(const float* __restrict__ f, int n4) {
    int i = blockIdx.x * blockDim.x + threadIdx.x;
    if (i < n4) {
        float4 v = reinterpret_cast<const float4*>(f)[i];
        __nv_bfloat162* dst = reinterpret_cast<__nv_bfloat162*>(g_feat_bf16);
        dst[i * 2]     = __floats2bfloat162_rn(v.x, v.y);
        dst[i * 2 + 1] = __floats2bfloat162_rn(v.z, v.w);
    }
}

__global__ void hx_prep_w1(const float* __restrict__ W1) {
    int idx = blockIdx.x * blockDim.x + threadIdx.x;   // 32768
    int k = idx >> 7, n = idx & 127;
    int c = n >> 3;
    int cs = (c & 8) | ((c & 7) ^ (k & 7));
    uint32_t off = (uint32_t)k * 256u + (uint32_t)cs * 16u + (uint32_t)(n & 7) * 2u;
    *reinterpret_cast<__nv_bfloat16*>(reinterpret_cast<char*>(g_w1_img) + off) =
        __float2bfloat16(W1[idx]);
}

__global__ void hx_final_kernel(float* out, int E) {
    out[0] = (float)(-g_loss_sum / (double)E);
}

// ---------------- device helpers ----------------
__device__ __forceinline__ void prefetch_idx(
    int t, int E, const int* __restrict__ row, const int* __restrict__ col,
    const int* __restrict__ label, int el, int h, int rem, int& nid, int& yv)
{
    int e = t * TILE_E + el;
    if (e >= E) e = 0;
    const int r = row[e];
    const int c = col[e];
    nid = h ? c : r;
    yv = 0;
    if (rem == 0) yv = (label[r] == label[c]) ? 1 : 0;
}

__device__ __forceinline__ void gather_issue(uint32_t Abuf, int nid,
                                             int el, int h, int part)
{
    const char* src = reinterpret_cast<const char*>(g_feat_bf16) + (size_t)nid * 256;
    const uint32_t rowbase = Abuf + (uint32_t)el * 512u;
    const int x = el & 7;
    #pragma unroll
    for (int ii = 0; ii < 8; ++ii) {
        const int i  = part * 8 + ii;
        const int c  = h * 16 + i;
        const int cs = (c & 24) | ((c & 7) ^ x);
        asm volatile("cp.async.cg.shared.global [%0], [%1], 16;"
                     :: "r"(rowbase + (uint32_t)cs * 16u), "l"(src + i * 16) : "memory");
    }
}

#define LDSM_X4(r, addr) \
    asm volatile("ldmatrix.sync.aligned.m8n8.x4.shared.b16 {%0,%1,%2,%3}, [%4];" \
        : "=r"((r)[0]), "=r"((r)[1]), "=r"((r)[2]), "=r"((r)[3]) : "r"(addr))
#define LDSM_X4T(r, addr) \
    asm volatile("ldmatrix.sync.aligned.m8n8.x4.trans.shared.b16 {%0,%1,%2,%3}, [%4];" \
        : "=r"((r)[0]), "=r"((r)[1]), "=r"((r)[2]), "=r"((r)[3]) : "r"(addr))

// ---------------- main persistent kernel ----------------
__global__ __launch_bounds__(THREADS, 1)
void hx_main_kernel(const float* __restrict__ b1,
                    const float* __restrict__ alpha,
                    const float* __restrict__ W2,
                    const float* __restrict__ b2,
                    const int* __restrict__ row,
                    const int* __restrict__ col,
                    const int* __restrict__ label,
                    int E, int ntiles)
{
    extern __shared__ char dyn[];
    __shared__ float s_b1[NHID], s_al[NHID], s_w20[NHID], s_w21[NHID];
    __shared__ float s_part0[4][TILE_E], s_part1[4][TILE_E];
    __shared__ int   s_y[4][TILE_E];
    __shared__ double s_dsum;

    const int tid  = threadIdx.x;
    const int lane = tid & 31;
    const int warp = tid >> 5;

    const uint32_t dynb = smem_u32(dyn);
    const uint32_t base = (dynb + 255u) & ~255u;
    const uint32_t Bsm  = base;
    const uint32_t Asm0 = base + B_BYTES;

    if (tid == 0) s_dsum = 0.0;
    if (tid < NHID) {
        s_b1[tid]  = b1[tid];
        s_al[tid]  = alpha[tid];
        s_w20[tid] = W2[2 * tid];
        s_w21[tid] = W2[2 * tid + 1];
    }
    {   // stage W1 image
        char* dst = dyn + (base - dynb);
        const int4* s = reinterpret_cast<const int4*>(g_w1_img);
        int4* d = reinterpret_cast<int4*>(dst);
        for (int i = tid; i < B_BYTES / 16; i += THREADS) d[i] = s[i];
    }

    const float bias0 = b2[0], bias1 = b2[1];

    const int g_el = tid >> 2, g_rem = tid & 3;
    const int g_h = g_rem >> 1, g_part = g_rem & 1;

    // 4x4 warp grid: warp tile m32 x n32
    const int warp_m = warp & 3, warp_n = warp >> 2;
    const int m_base = warp_m * 32, n_base = warp_n * 32;

    // A fragment addresses: for m-strip i and k-step ks,
    //   addr = Abuf + rowA[i] + csel(ks, xA[i]) * 16
    uint32_t rowA[2]; int xA[2];
    #pragma unroll
    for (int i = 0; i < 2; ++i) {
        const int r = m_base + i * 16 + (lane & 15);
        rowA[i] = (uint32_t)r * 512u;
        xA[i]   = r & 7;
    }
    const int csA = lane >> 4;

    uint32_t bBase[2];
    {
        const int kr = lane & 15;
        const int xB = lane & 7;
        #pragma unroll
        for (int j2 = 0; j2 < 2; ++j2) {
            const int cn = warp_n * 4 + j2 * 2 + (lane >> 4);
            const int cs = (cn & 8) | ((cn & 7) ^ xB);
            bBase[j2] = Bsm + (uint32_t)kr * 256u + (uint32_t)cs * 16u;
        }
    }

    const int grid = gridDim.x;
    double dsum = 0.0;

    // ---- pipeline warm-up ----
    int nidN = 0, yvN = 0;
    if (blockIdx.x < ntiles) {
        int nid0, yv0;
        prefetch_idx(blockIdx.x, E, row, col, label, g_el, g_h, g_rem, nid0, yv0);
        if (g_rem == 0) s_y[0][g_el] = yv0;
        gather_issue(Asm0, nid0, g_el, g_h, g_part);
        asm volatile("cp.async.commit_group;" ::: "memory");
        if (blockIdx.x + grid < ntiles)
            prefetch_idx(blockIdx.x + grid, E, row, col, label, g_el, g_h, g_rem, nidN, yvN);
    }

    int li = 0;
    for (int t = blockIdx.x; t < ntiles; t += grid, ++li) {
        const int buf = li & 1;
        const uint32_t Abuf = Asm0 + (uint32_t)buf * A_BYTES;
        const int tn = t + grid;

        if (tn < ntiles) {
            if (g_rem == 0) s_y[(li + 1) & 3][g_el] = yvN;
            gather_issue(Asm0 + (uint32_t)(buf ^ 1) * A_BYTES, nidN, g_el, g_h, g_part);
            asm volatile("cp.async.commit_group;" ::: "memory");
            asm volatile("cp.async.wait_group 1;" ::: "memory");
            if (t + 2 * grid < ntiles)
                prefetch_idx(t + 2 * grid, E, row, col, label, g_el, g_h, g_rem, nidN, yvN);
        } else {
            asm volatile("cp.async.wait_group 0;" ::: "memory");
        }
        __syncthreads();

        // ---- GEMM: 16 k-steps, explicit 2-stage fragment pipeline ----
        float acc[2][4][4];
        #pragma unroll
        for (int i = 0; i < 2; ++i)
            #pragma unroll
            for (int j = 0; j < 4; ++j) {
                acc[i][j][0] = 0.f; acc[i][j][1] = 0.f;
                acc[i][j][2] = 0.f; acc[i][j][3] = 0.f;
            }

        uint32_t aF[2][2][4], bF[2][2][4];

        // prime ks = 0 into buffer 0
        {
            const int c0 = csA;
            #pragma unroll
            for (int i = 0; i < 2; ++i) {
                const int cs = (c0 & 24) | ((c0 & 7) ^ xA[i]);
                LDSM_X4(aF[0][i], Abuf + rowA[i] + (uint32_t)cs * 16u);
            }
            #pragma unroll
            for (int j2 = 0; j2 < 2; ++j2)
                LDSM_X4T(bF[0][j2], bBase[j2]);
        }

        #pragma unroll
        for (int ks = 0; ks < 16; ++ks) {
            const int cb = ks & 1, nb = cb ^ 1;
            if (ks < 15) {   // prefetch ks+1 before consuming ks
                const int c = 2 * (ks + 1) + csA;
                #pragma unroll
                for (int i = 0; i < 2; ++i) {
                    const int cs = (c & 24) | ((c & 7) ^ xA[i]);
                    LDSM_X4(aF[nb][i], Abuf + rowA[i] + (uint32_t)cs * 16u);
                }
                #pragma unroll
                for (int j2 = 0; j2 < 2; ++j2)
                    LDSM_X4T(bF[nb][j2], bBase[j2] + (uint32_t)(ks + 1) * 4096u);
            }
            #pragma unroll
            for (int i = 0; i < 2; ++i)
                #pragma unroll
                for (int j = 0; j < 4; ++j) {
                    const uint32_t bb0 = bF[cb][j >> 1][(j & 1) * 2];
                    const uint32_t bb1 = bF[cb][j >> 1][(j & 1) * 2 + 1];
                    asm volatile(
                        "mma.sync.aligned.m16n8k16.row.col.f32.bf16.bf16.f32 "
                        "{%0,%1,%2,%3}, {%4,%5,%6,%7}, {%8,%9}, {%0,%1,%2,%3};"
                        : "+f"(acc[i][j][0]), "+f"(acc[i][j][1]),
                          "+f"(acc[i][j][2]), "+f"(acc[i][j][3])
                        : "r"(aF[cb][i][0]), "r"(aF[cb][i][1]),
                          "r"(aF[cb][i][2]), "r"(aF[cb][i][3]),
                          "r"(bb0), "r"(bb1));
                }
        }

        // ---- fragment epilogue: PReLU + 128->2 projection ----
        const int quad = lane >> 2, qlane = lane & 3;
        float pr0[4], pr1[4];
        #pragma unroll
        for (int i = 0; i < 4; ++i) { pr0[i] = 0.f; pr1[i] = 0.f; }

        #pragma unroll
        for (int j = 0; j < 4; ++j) {
            const int n = n_base + j * 8 + qlane * 2;
            const float bv0 = s_b1[n],  bv1 = s_b1[n + 1];
            const float av0 = s_al[n],  av1 = s_al[n + 1];
            const float wa0 = s_w20[n], wa1 = s_w20[n + 1];
            const float wb0 = s_w21[n], wb1 = s_w21[n + 1];
            #pragma unroll
            for (int i = 0; i < 2; ++i) {
                float h;
                h = acc[i][j][0] + bv0; h = h >= 0.f ? h : av0 * h;
                pr0[i*2]   = fmaf(h, wa0, pr0[i*2]);   pr1[i*2]   = fmaf(h, wb0, pr1[i*2]);
                h = acc[i][j][1] + bv1; h = h >= 0.f ? h : av1 * h;
                pr0[i*2]   = fmaf(h, wa1, pr0[i*2]);   pr1[i*2]   = fmaf(h, wb1, pr1[i*2]);
                h = acc[i][j][2] + bv0; h = h >= 0.f ? h : av0 * h;
                pr0[i*2+1] = fmaf(h, wa0, pr0[i*2+1]); pr1[i*2+1] = fmaf(h, wb0, pr1[i*2+1]);
                h = acc[i][j][3] + bv1; h = h >= 0.f ? h : av1 * h;
                pr0[i*2+1] = fmaf(h, wa1, pr0[i*2+1]); pr1[i*2+1] = fmaf(h, wb1, pr1[i*2+1]);
            }
        }
        #pragma unroll
        for (int i = 0; i < 4; ++i) {
            pr0[i] += __shfl_xor_sync(0xffffffffu, pr0[i], 1);
            pr0[i] += __shfl_xor_sync(0xffffffffu, pr0[i], 2);
            pr1[i] += __shfl_xor_sync(0xffffffffu, pr1[i], 1);
            pr1[i] += __shfl_xor_sync(0xffffffffu, pr1[i], 2);
        }
        if (qlane == 0) {
            #pragma unroll
            for (int i = 0; i < 2; ++i) {
                const int r0 = m_base + i * 16 + quad;
                s_part0[warp_n][r0]     = pr0[i*2];   s_part1[warp_n][r0]     = pr1[i*2];
                s_part0[warp_n][r0 + 8] = pr0[i*2+1]; s_part1[warp_n][r0 + 8] = pr1[i*2+1];
            }
        }
        __syncthreads();

        if (tid < TILE_E) {
            const int e = t * TILE_E + tid;
            if (e < E) {
                const float l0 = s_part0[0][tid] + s_part0[1][tid]
                               + s_part0[2][tid] + s_part0[3][tid] + bias0;
                const float l1 = s_part1[0][tid] + s_part1[1][tid]
                               + s_part1[2][tid] + s_part1[3][tid] + bias1;
                const int y   = s_y[li & 3][tid];
                const float mx  = fmaxf(l0, l1);
                const float lse = mx + log1pf(expf(-fabsf(l0 - l1)));
                dsum += (double)((y ? l1 : l0) - lse);
            }
        }
    }

    __syncthreads();
    if (tid < TILE_E) atomicAdd(&s_dsum, dsum);
    __syncthreads();
    if (tid == 0) atomicAdd(&g_loss_sum, s_dsum);
}

extern "C" void kernel_launch(void* const* d_in, const int* in_sizes, int n_in,
                              void* d_out, int out_size) {
    const float* feature = (const float*)d_in[0];
    const float* W1      = (const float*)d_in[1];
    const float* b1      = (const float*)d_in[2];
    const float* alpha   = (const float*)d_in[3];
    const float* W2      = (const float*)d_in[4];
    const float* b2      = (const float*)d_in[5];
    const int*   row     = (const int*)d_in[6];
    const int*   col     = (const int*)d_in[7];
    const int*   label   = (const int*)d_in[8];
    const int E  = in_sizes[6];
    const int nf = in_sizes[0];
    float* out = (float*)d_out;

    int sms = 148;
    cudaDeviceGetAttribute(&sms, cudaDevAttrMultiProcessorCount, 0);
    cudaFuncSetAttribute(hx_main_kernel,
                         cudaFuncAttributeMaxDynamicSharedMemorySize, DSMEM);

    hx_init_kernel<<<1, 1>>>();
    hx_prep_feat<<<(nf / 4 + 255) / 256, 256>>>(feature, nf / 4);
    hx_prep_w1<<<(KDIM * NHID) / 256, 256>>>(W1);

    const int ntiles = (E + TILE_E - 1) / TILE_E;
    hx_main_kernel<<<sms, THREADS, DSMEM>>>(b1, alpha, W2, b2, row, col, label, E, ntiles);
    hx_final_kernel<<<1, 1>>>(out, E);
}

// round 7
// speedup vs baseline: 1.3773x; 1.3773x over previous
#include <cuda_runtime.h>
#include <cuda_bf16.h>
#include <cstdint>

// Fused edge-MLP CE loss via warp-level bf16 mma.sync.
// R7: warp-coherent gather (each cp.async warp-instr = 2 whole 256B node rows,
// node ids via smem ring) -> ~8x fewer L1tex wavefronts; softmax spread over
// all 16 warps. GEMM/epilogue math identical to R5.

namespace {
constexpr int NHID    = 128;
constexpr int KDIM    = 256;
constexpr int TILE_E  = 128;
constexpr int THREADS = 512;
constexpr int A_BYTES = TILE_E * KDIM * 2;
constexpr int B_BYTES = KDIM * NHID * 2;
constexpr int DSMEM   = B_BYTES + 2 * A_BYTES + 256;
}

__device__ __align__(16) __nv_bfloat16 g_feat_bf16[(size_t)100000 * NHID];
__device__ __align__(16) __nv_bfloat16 g_w1_img[KDIM * NHID];
__device__ double g_loss_sum;

__device__ __forceinline__ uint32_t smem_u32(const void* p) {
    uint32_t a;
    asm("{ .reg .u64 t; cvta.to.shared.u64 t, %1; cvt.u32.u64 %0, t; }" : "=r"(a) : "l"(p));
    return a;
}

// ---------------- prep kernels ----------------
__global__ void hx_init_kernel() { g_loss_sum = 0.0; }

__global__ void hx_prep_feat(const float* __restrict__ f, int n4) {
    int i = blockIdx.x * blockDim.x + threadIdx.x;
    if (i < n4) {
        float4 v = reinterpret_cast<const float4*>(f)[i];
        __nv_bfloat162* dst = reinterpret_cast<__nv_bfloat162*>(g_feat_bf16);
        dst[i * 2]     = __floats2bfloat162_rn(v.x, v.y);
        dst[i * 2 + 1] = __floats2bfloat162_rn(v.z, v.w);
    }
}

__global__ void hx_prep_w1(const float* __restrict__ W1) {
    int idx = blockIdx.x * blockDim.x + threadIdx.x;   // 32768
    int k = idx >> 7, n = idx & 127;
    int c = n >> 3;
    int cs = (c & 8) | ((c & 7) ^ (k & 7));
    uint32_t off = (uint32_t)k * 256u + (uint32_t)cs * 16u + (uint32_t)(n & 7) * 2u;
    *reinterpret_cast<__nv_bfloat16*>(reinterpret_cast<char*>(g_w1_img) + off) =
        __float2bfloat16(W1[idx]);
}

__global__ void hx_final_kernel(float* out, int E) {
    out[0] = (float)(-g_loss_sum / (double)E);
}

// ---------------- device helpers ----------------
// Prefetch tile tp's node ids + edge labels into smem ring (256 threads).
// rowidx = el*2 + h  (h: 0=row endpoint, 1=col endpoint)
__device__ __forceinline__ void prefetch_tile(
    int tp, int E, const int* __restrict__ row, const int* __restrict__ col,
    const int* __restrict__ label, int tid, int* __restrict__ s_nid,
    int* __restrict__ s_yrow)
{
    if (tid < 2 * TILE_E) {
        const int el = tid >> 1, h = tid & 1;
        int e = tp * TILE_E + el;
        if (e >= E) e = 0;
        const int r = row[e], c = col[e];
        s_nid[tid] = h ? c : r;
        if (h == 0) s_yrow[el] = (label[r] == label[c]) ? 1 : 0;
    }
}

// Warp-coherent gather: each iteration, the warp loads 2 complete 256B node
// rows (lanes 0-15 -> first row, 16-31 -> second), cp.async into swizzled A.
__device__ __forceinline__ void gather_issue_warp(
    uint32_t Abuf, const int* __restrict__ s_nid, int warp, int lane)
{
    const int half = lane >> 4;
    const int i    = lane & 15;          // 16B chunk within the 256B row
    #pragma unroll
    for (int j = 0; j < 8; ++j) {
        const int rowidx = warp * 16 + j * 2 + half;
        const int el = rowidx >> 1, h = rowidx & 1;
        const int nid = s_nid[rowidx];
        const int c  = h * 16 + i;
        const int cs = (c & 24) | ((c & 7) ^ (el & 7));
        const char* src = reinterpret_cast<const char*>(g_feat_bf16)
                        + (size_t)nid * 256 + i * 16;
        asm volatile("cp.async.cg.shared.global [%0], [%1], 16;"
                     :: "r"(Abuf + (uint32_t)el * 512u + (uint32_t)cs * 16u),
                        "l"(src) : "memory");
    }
}

// ---------------- main persistent kernel ----------------
__global__ __launch_bounds__(THREADS, 1)
void hx_main_kernel(const float* __restrict__ b1,
                    const float* __restrict__ alpha,
                    const float* __restrict__ W2,
                    const float* __restrict__ b2,
                    const int* __restrict__ row,
                    const int* __restrict__ col,
                    const int* __restrict__ label,
                    int E, int ntiles)
{
    extern __shared__ char dyn[];
    __shared__ float s_b1[NHID], s_al[NHID], s_w20[NHID], s_w21[NHID];
    __shared__ float s_part0[4][TILE_E], s_part1[4][TILE_E];
    __shared__ int   s_nid[2][2 * TILE_E];   // nid ring (depth 2)
    __shared__ int   s_y[4][TILE_E];         // y ring (depth 4)
    __shared__ double s_dsum;

    const int tid  = threadIdx.x;
    const int lane = tid & 31;
    const int warp = tid >> 5;

    const uint32_t dynb = smem_u32(dyn);
    const uint32_t base = (dynb + 255u) & ~255u;
    const uint32_t Bsm  = base;
    const uint32_t Asm0 = base + B_BYTES;

    if (tid == 0) s_dsum = 0.0;
    if (tid < NHID) {
        s_b1[tid]  = b1[tid];
        s_al[tid]  = alpha[tid];
        s_w20[tid] = W2[2 * tid];
        s_w21[tid] = W2[2 * tid + 1];
    }
    {   // stage W1 image
        char* dst = dyn + (base - dynb);
        const int4* s = reinterpret_cast<const int4*>(g_w1_img);
        int4* d = reinterpret_cast<int4*>(dst);
        for (int i = tid; i < B_BYTES / 16; i += THREADS) d[i] = s[i];
    }

    const float bias0 = b2[0], bias1 = b2[1];

    // 4x4 warp grid: warp tile m32 x n32
    const int warp_m = warp & 3, warp_n = warp >> 2;
    const int m_base = warp_m * 32, n_base = warp_n * 32;

    uint32_t rowA[2]; int xA[2];
    #pragma unroll
    for (int i = 0; i < 2; ++i) {
        const int r = m_base + i * 16 + (lane & 15);
        rowA[i] = (uint32_t)r * 512u;
        xA[i]   = r & 7;
    }
    const int csA = lane >> 4;

    uint32_t bBase[2];
    {
        const int kr = lane & 15;
        const int xB = lane & 7;
        #pragma unroll
        for (int j2 = 0; j2 < 2; ++j2) {
            const int cn = warp_n * 4 + j2 * 2 + (lane >> 4);
            const int cs = (cn & 8) | ((cn & 7) ^ xB);
            bBase[j2] = Bsm + (uint32_t)kr * 256u + (uint32_t)cs * 16u;
        }
    }

    const int grid = gridDim.x;
    double dsum = 0.0;

    // ---- warm-up: nid(t0) -> gather(t0); nid(t1) staged ----
    prefetch_tile(blockIdx.x, E, row, col, label, tid, s_nid[0], s_y[0]);
    __syncthreads();
    if (blockIdx.x < ntiles) {
        gather_issue_warp(Asm0, s_nid[0], warp, lane);
        asm volatile("cp.async.commit_group;" ::: "memory");
        if (blockIdx.x + grid < ntiles)
            prefetch_tile(blockIdx.x + grid, E, row, col, label, tid, s_nid[1], s_y[1]);
    }
    __syncthreads();

    int li = 0;
    for (int t = blockIdx.x; t < ntiles; t += grid, ++li) {
        const int buf = li & 1;
        const uint32_t Abuf = Asm0 + (uint32_t)buf * A_BYTES;
        const int tn = t + grid;

        if (tn < ntiles) {
            gather_issue_warp(Asm0 + (uint32_t)(buf ^ 1) * A_BYTES,
                              s_nid[(li + 1) & 1], warp, lane);
            asm volatile("cp.async.commit_group;" ::: "memory");
            asm volatile("cp.async.wait_group 1;" ::: "memory");
        } else {
            asm volatile("cp.async.wait_group 0;" ::: "memory");
        }
        __syncthreads();

        // prefetch nid/y for tile t+2*grid (overlaps GEMM; ring slots safe:
        // writes slot li&1, which is next read after the post-epilogue barrier)
        if (t + 2 * grid < ntiles)
            prefetch_tile(t + 2 * grid, E, row, col, label, tid,
                          s_nid[li & 1], s_y[(li + 2) & 3]);

        // ---- GEMM: 16 k-steps of m16n8k16, warp tile m32n32 ----
        float acc[2][4][4];
        #pragma unroll
        for (int i = 0; i < 2; ++i)
            #pragma unroll
            for (int j = 0; j < 4; ++j) {
                acc[i][j][0] = 0.f; acc[i][j][1] = 0.f;
                acc[i][j][2] = 0.f; acc[i][j][3] = 0.f;
            }

        #pragma unroll
        for (int ks = 0; ks < 16; ++ks) {
            uint32_t a[2][4];
            #pragma unroll
            for (int i = 0; i < 2; ++i) {
                const int c  = 2 * ks + csA;
                const int cs = (c & 24) | ((c & 7) ^ xA[i]);
                const uint32_t addr = Abuf + rowA[i] + (uint32_t)cs * 16u;
                asm volatile("ldmatrix.sync.aligned.m8n8.x4.shared.b16 {%0,%1,%2,%3}, [%4];"
                    : "=r"(a[i][0]), "=r"(a[i][1]), "=r"(a[i][2]), "=r"(a[i][3]) : "r"(addr));
            }
            uint32_t b[2][4];
            #pragma unroll
            for (int j2 = 0; j2 < 2; ++j2) {
                const uint32_t addr = bBase[j2] + (uint32_t)ks * 4096u;
                asm volatile("ldmatrix.sync.aligned.m8n8.x4.trans.shared.b16 {%0,%1,%2,%3}, [%4];"
                    : "=r"(b[j2][0]), "=r"(b[j2][1]), "=r"(b[j2][2]), "=r"(b[j2][3]) : "r"(addr));
            }
            #pragma unroll
            for (int i = 0; i < 2; ++i)
                #pragma unroll
                for (int j = 0; j < 4; ++j) {
                    const uint32_t bb0 = b[j >> 1][(j & 1) * 2];
                    const uint32_t bb1 = b[j >> 1][(j & 1) * 2 + 1];
                    asm volatile(
                        "mma.sync.aligned.m16n8k16.row.col.f32.bf16.bf16.f32 "
                        "{%0,%1,%2,%3}, {%4,%5,%6,%7}, {%8,%9}, {%0,%1,%2,%3};"
                        : "+f"(acc[i][j][0]), "+f"(acc[i][j][1]),
                          "+f"(acc[i][j][2]), "+f"(acc[i][j][3])
                        : "r"(a[i][0]), "r"(a[i][1]), "r"(a[i][2]), "r"(a[i][3]),
                          "r"(bb0), "r"(bb1));
                }
        }

        // ---- fragment epilogue: PReLU + 128->2 projection ----
        const int quad = lane >> 2, qlane = lane & 3;
        float pr0[4], pr1[4];
        #pragma unroll
        for (int i = 0; i < 4; ++i) { pr0[i] = 0.f; pr1[i] = 0.f; }

        #pragma unroll
        for (int j = 0; j < 4; ++j) {
            const int n = n_base + j * 8 + qlane * 2;
            const float bv0 = s_b1[n],  bv1 = s_b1[n + 1];
            const float av0 = s_al[n],  av1 = s_al[n + 1];
            const float wa0 = s_w20[n], wa1 = s_w20[n + 1];
            const float wb0 = s_w21[n], wb1 = s_w21[n + 1];
            #pragma unroll
            for (int i = 0; i < 2; ++i) {
                float h;
                h = acc[i][j][0] + bv0; h = h >= 0.f ? h : av0 * h;
                pr0[i*2]   = fmaf(h, wa0, pr0[i*2]);   pr1[i*2]   = fmaf(h, wb0, pr1[i*2]);
                h = acc[i][j][1] + bv1; h = h >= 0.f ? h : av1 * h;
                pr0[i*2]   = fmaf(h, wa1, pr0[i*2]);   pr1[i*2]   = fmaf(h, wb1, pr1[i*2]);
                h = acc[i][j][2] + bv0; h = h >= 0.f ? h : av0 * h;
                pr0[i*2+1] = fmaf(h, wa0, pr0[i*2+1]); pr1[i*2+1] = fmaf(h, wb0, pr1[i*2+1]);
                h = acc[i][j][3] + bv1; h = h >= 0.f ? h : av1 * h;
                pr0[i*2+1] = fmaf(h, wa1, pr0[i*2+1]); pr1[i*2+1] = fmaf(h, wb1, pr1[i*2+1]);
            }
        }
        #pragma unroll
        for (int i = 0; i < 4; ++i) {
            pr0[i] += __shfl_xor_sync(0xffffffffu, pr0[i], 1);
            pr0[i] += __shfl_xor_sync(0xffffffffu, pr0[i], 2);
            pr1[i] += __shfl_xor_sync(0xffffffffu, pr1[i], 1);
            pr1[i] += __shfl_xor_sync(0xffffffffu, pr1[i], 2);
        }
        if (qlane == 0) {
            #pragma unroll
            for (int i = 0; i < 2; ++i) {
                const int r0 = m_base + i * 16 + quad;
                s_part0[warp_n][r0]     = pr0[i*2];   s_part1[warp_n][r0]     = pr1[i*2];
                s_part0[warp_n][r0 + 8] = pr0[i*2+1]; s_part1[warp_n][r0 + 8] = pr1[i*2+1];
            }
        }
        __syncthreads();

        // ---- per-edge log-softmax + NLL, spread over all 16 warps ----
        if (lane < 8) {
            const int m = warp * 8 + lane;
            const int e = t * TILE_E + m;
            if (e < E) {
                const float l0 = s_part0[0][m] + s_part0[1][m]
                               + s_part0[2][m] + s_part0[3][m] + bias0;
                const float l1 = s_part1[0][m] + s_part1[1][m]
                               + s_part1[2][m] + s_part1[3][m] + bias1;
                const int y   = s_y[li & 3][m];
                const float mx  = fmaxf(l0, l1);
                const float lse = mx + log1pf(expf(-fabsf(l0 - l1)));
                dsum += (double)((y ? l1 : l0) - lse);
            }
        }
    }

    __syncthreads();
    if (lane < 8) atomicAdd(&s_dsum, dsum);
    __syncthreads();
    if (tid == 0) atomicAdd(&g_loss_sum, s_dsum);
}

extern "C" void kernel_launch(void* const* d_in, const int* in_sizes, int n_in,
                              void* d_out, int out_size) {
    const float* feature = (const float*)d_in[0];
    const float* W1      = (const float*)d_in[1];
    const float* b1      = (const float*)d_in[2];
    const float* alpha   = (const float*)d_in[3];
    const float* W2      = (const float*)d_in[4];
    const float* b2      = (const float*)d_in[5];
    const int*   row     = (const int*)d_in[6];
    const int*   col     = (const int*)d_in[7];
    const int*   label   = (const int*)d_in[8];
    const int E  = in_sizes[6];
    const int nf = in_sizes[0];
    float* out = (float*)d_out;

    int sms = 148;
    cudaDeviceGetAttribute(&sms, cudaDevAttrMultiProcessorCount, 0);
    cudaFuncSetAttribute(hx_main_kernel,
                         cudaFuncAttributeMaxDynamicSharedMemorySize, DSMEM);

    hx_init_kernel<<<1, 1>>>();
    hx_prep_feat<<<(nf / 4 + 255) / 256, 256>>>(feature, nf / 4);
    hx_prep_w1<<<(KDIM * NHID) / 256, 256>>>(W1);

    const int ntiles = (E + TILE_E - 1) / TILE_E;
    hx_main_kernel<<<sms, THREADS, DSMEM>>>(b1, alpha, W2, b2, row, col, label, E, ntiles);
    hx_final_kernel<<<1, 1>>>(out, E);
}

// round 8
// speedup vs baseline: 1.4943x; 1.0850x over previous
#include <cuda_runtime.h>
#include <cuda_bf16.h>
#include <cstdint>

// Fused edge-MLP CE loss via warp-level bf16 mma.sync.
// R8: two independent 8-warp groups per CTA, each on its own 128-edge tile
// with m64n32 warp tiles (2m x 4n). 23% less LDSM traffic; groups sync only
// via named barriers so GEMM of one group hides gather/epilogue of the other.

namespace {
constexpr int NHID    = 128;
constexpr int KDIM    = 256;
constexpr int TILE_E  = 128;
constexpr int THREADS = 512;
constexpr int A_BYTES = TILE_E * KDIM * 2;   // 64 KB per group A buffer
constexpr int B_BYTES = KDIM * NHID * 2;     // 64 KB W1 image
constexpr int DSMEM   = B_BYTES + 2 * A_BYTES + 256;
}

__device__ __align__(16) __nv_bfloat16 g_feat_bf16[(size_t)100000 * NHID];
__device__ __align__(16) __nv_bfloat16 g_w1_img[KDIM * NHID];
__device__ double g_loss_sum;

__device__ __forceinline__ uint32_t smem_u32(const void* p) {
    uint32_t a;
    asm("{ .reg .u64 t; cvta.to.shared.u64 t, %1; cvt.u32.u64 %0, t; }" : "=r"(a) : "l"(p));
    return a;
}

#define GBAR(id) asm volatile("bar.sync %0, 256;" :: "r"(id) : "memory")

#define LDSM_X4(r, addr) \
    asm volatile("ldmatrix.sync.aligned.m8n8.x4.shared.b16 {%0,%1,%2,%3}, [%4];" \
        : "=r"((r)[0]), "=r"((r)[1]), "=r"((r)[2]), "=r"((r)[3]) : "r"(addr))
#define LDSM_X4T(r, addr) \
    asm volatile("ldmatrix.sync.aligned.m8n8.x4.trans.shared.b16 {%0,%1,%2,%3}, [%4];" \
        : "=r"((r)[0]), "=r"((r)[1]), "=r"((r)[2]), "=r"((r)[3]) : "r"(addr))

// ---------------- prep kernels ----------------
__global__ void hx_init_kernel() { g_loss_sum = 0.0; }

__global__ void hx_prep_feat(const float* __restrict__ f, int n4) {
    int i = blockIdx.x * blockDim.x + threadIdx.x;
    if (i < n4) {
        float4 v = reinterpret_cast<const float4*>(f)[i];
        __nv_bfloat162* dst = reinterpret_cast<__nv_bfloat162*>(g_feat_bf16);
        dst[i * 2]     = __floats2bfloat162_rn(v.x, v.y);
        dst[i * 2 + 1] = __floats2bfloat162_rn(v.z, v.w);
    }
}

__global__ void hx_prep_w1(const float* __restrict__ W1) {
    int idx = blockIdx.x * blockDim.x + threadIdx.x;   // 32768
    int k = idx >> 7, n = idx & 127;
    int c = n >> 3;
    int cs = (c & 8) | ((c & 7) ^ (k & 7));
    uint32_t off = (uint32_t)k * 256u + (uint32_t)cs * 16u + (uint32_t)(n & 7) * 2u;
    *reinterpret_cast<__nv_bfloat16*>(reinterpret_cast<char*>(g_w1_img) + off) =
        __float2bfloat16(W1[idx]);
}

__global__ void hx_final_kernel(float* out, int E) {
    out[0] = (float)(-g_loss_sum / (double)E);
}

// ---------------- device helpers ----------------
__device__ __forceinline__ void prefetch_tile(
    int tp, int E, const int* __restrict__ row, const int* __restrict__ col,
    const int* __restrict__ label, int gtid, int* __restrict__ s_nid,
    int* __restrict__ s_yrow)
{
    const int el = gtid >> 1, h = gtid & 1;
    int e = tp * TILE_E + el;
    if (e >= E) e = 0;
    const int r = row[e], c = col[e];
    s_nid[gtid] = h ? c : r;
    if (h == 0) s_yrow[el] = (label[r] == label[c]) ? 1 : 0;
}

// Warp-coherent gather: warp wg (0..7 in group) loads 32 of the 256 node rows.
__device__ __forceinline__ void gather_issue_warp(
    uint32_t Abuf, const int* __restrict__ s_nid, int wg, int lane)
{
    const int half = lane >> 4;
    const int i    = lane & 15;
    #pragma unroll
    for (int j = 0; j < 16; ++j) {
        const int rowidx = wg * 32 + j * 2 + half;
        const int el = rowidx >> 1, h = rowidx & 1;
        const int nid = s_nid[rowidx];
        const int c  = h * 16 + i;
        const int cs = (c & 24) | ((c & 7) ^ (el & 7));
        const char* src = reinterpret_cast<const char*>(g_feat_bf16)
                        + (size_t)nid * 256 + i * 16;
        asm volatile("cp.async.cg.shared.global [%0], [%1], 16;"
                     :: "r"(Abuf + (uint32_t)el * 512u + (uint32_t)cs * 16u),
                        "l"(src) : "memory");
    }
}

// ---------------- main persistent kernel ----------------
__global__ __launch_bounds__(THREADS, 1)
void hx_main_kernel(const float* __restrict__ b1,
                    const float* __restrict__ alpha,
                    const float* __restrict__ W2,
                    const float* __restrict__ b2,
                    const int* __restrict__ row,
                    const int* __restrict__ col,
                    const int* __restrict__ label,
                    int E, int ntiles)
{
    extern __shared__ char dyn[];
    __shared__ float s_b1[NHID], s_al[NHID], s_w20[NHID], s_w21[NHID];
    __shared__ float s_part0[2][4][TILE_E], s_part1[2][4][TILE_E];
    __shared__ int   s_nid[2][2][2 * TILE_E];
    __shared__ int   s_y[2][4][TILE_E];
    __shared__ double s_dsum;

    const int tid  = threadIdx.x;
    const int lane = tid & 31;
    const int warp = tid >> 5;
    const int grp  = warp >> 3;          // 0 or 1
    const int wg   = warp & 7;           // warp within group
    const int gtid = tid & 255;          // thread within group
    const int barid = 1 + grp;

    const uint32_t dynb = smem_u32(dyn);
    const uint32_t base = (dynb + 255u) & ~255u;
    const uint32_t Bsm  = base;
    const uint32_t Abuf = base + B_BYTES + (uint32_t)grp * A_BYTES;

    if (tid == 0) s_dsum = 0.0;
    if (tid < NHID) {
        s_b1[tid]  = b1[tid];
        s_al[tid]  = alpha[tid];
        s_w20[tid] = W2[2 * tid];
        s_w21[tid] = W2[2 * tid + 1];
    }
    {   // stage W1 image
        char* dst = dyn + (base - dynb);
        const int4* s = reinterpret_cast<const int4*>(g_w1_img);
        int4* d = reinterpret_cast<int4*>(dst);
        for (int i = tid; i < B_BYTES / 16; i += THREADS) d[i] = s[i];
    }

    const float bias0 = b2[0], bias1 = b2[1];

    // warp tile m64 x n32: group grid 2m x 4n
    const int warp_m = wg & 1, warp_n = wg >> 1;
    const int m_base = warp_m * 64, n_base = warp_n * 32;

    // A fragment bases: rows m_base + i*16 + (lane&15), i in 0..3
    uint32_t rowA[4];
    #pragma unroll
    for (int i = 0; i < 4; ++i)
        rowA[i] = (uint32_t)(m_base + i * 16 + (lane & 15)) * 512u;
    const int xA  = lane & 7;
    const int csA = lane >> 4;

    uint32_t bBase[2];
    {
        const int kr = lane & 15;
        const int xB = lane & 7;
        #pragma unroll
        for (int j2 = 0; j2 < 2; ++j2) {
            const int cn = warp_n * 4 + j2 * 2 + (lane >> 4);
            const int cs = (cn & 8) | ((cn & 7) ^ xB);
            bBase[j2] = Bsm + (uint32_t)kr * 256u + (uint32_t)cs * 16u;
        }
    }

    const int stride = 2 * gridDim.x;
    const int t0 = 2 * blockIdx.x + grp;
    double dsum = 0.0;

    __syncthreads();   // B image + params ready (last block-wide barrier)

    // ---- per-group warm-up ----
    if (t0 < ntiles) {
        prefetch_tile(t0, E, row, col, label, gtid, s_nid[grp][0], s_y[grp][0]);
        GBAR(barid);
        gather_issue_warp(Abuf, s_nid[grp][0], wg, lane);
        asm volatile("cp.async.commit_group;" ::: "memory");
        if (t0 + stride < ntiles)
            prefetch_tile(t0 + stride, E, row, col, label, gtid,
                          s_nid[grp][1], s_y[grp][1]);
    }

    int li = 0;
    for (int t = t0; t < ntiles; t += stride, ++li) {
        asm volatile("cp.async.wait_group 0;" ::: "memory");
        GBAR(barid);

        // prefetch nid/y for t+2*stride during GEMM (slots distinct from reads)
        if (t + 2 * stride < ntiles)
            prefetch_tile(t + 2 * stride, E, row, col, label, gtid,
                          s_nid[grp][li & 1], s_y[grp][(li + 2) & 3]);

        // ---- GEMM: 16 k-steps, warp tile m64n32 ----
        float acc[4][4][4];
        #pragma unroll
        for (int i = 0; i < 4; ++i)
            #pragma unroll
            for (int j = 0; j < 4; ++j) {
                acc[i][j][0] = 0.f; acc[i][j][1] = 0.f;
                acc[i][j][2] = 0.f; acc[i][j][3] = 0.f;
            }

        #pragma unroll
        for (int ks = 0; ks < 16; ++ks) {
            uint32_t b[2][4];
            #pragma unroll
            for (int j2 = 0; j2 < 2; ++j2)
                LDSM_X4T(b[j2], bBase[j2] + (uint32_t)ks * 4096u);
            const int c  = 2 * ks + csA;
            const int cs = (c & 24) | ((c & 7) ^ xA);
            #pragma unroll
            for (int i = 0; i < 4; ++i) {
                uint32_t a[4];
                LDSM_X4(a, Abuf + rowA[i] + (uint32_t)cs * 16u);
                #pragma unroll
                for (int j = 0; j < 4; ++j) {
                    const uint32_t bb0 = b[j >> 1][(j & 1) * 2];
                    const uint32_t bb1 = b[j >> 1][(j & 1) * 2 + 1];
                    asm volatile(
                        "mma.sync.aligned.m16n8k16.row.col.f32.bf16.bf16.f32 "
                        "{%0,%1,%2,%3}, {%4,%5,%6,%7}, {%8,%9}, {%0,%1,%2,%3};"
                        : "+f"(acc[i][j][0]), "+f"(acc[i][j][1]),
                          "+f"(acc[i][j][2]), "+f"(acc[i][j][3])
                        : "r"(a[0]), "r"(a[1]), "r"(a[2]), "r"(a[3]),
                          "r"(bb0), "r"(bb1));
                }
            }
        }

        GBAR(barid);   // group done reading Abuf

        // ---- gather next tile immediately (lands during epilogue + other group) ----
        const int tn = t + stride;
        if (tn < ntiles) {
            gather_issue_warp(Abuf, s_nid[grp][(li + 1) & 1], wg, lane);
            asm volatile("cp.async.commit_group;" ::: "memory");
        }

        // ---- fragment epilogue: PReLU + 128->2 projection ----
        const int quad = lane >> 2, qlane = lane & 3;
        float pr0[8], pr1[8];
        #pragma unroll
        for (int i = 0; i < 8; ++i) { pr0[i] = 0.f; pr1[i] = 0.f; }

        #pragma unroll
        for (int j = 0; j < 4; ++j) {
            const int n = n_base + j * 8 + qlane * 2;
            const float bv0 = s_b1[n],  bv1 = s_b1[n + 1];
            const float av0 = s_al[n],  av1 = s_al[n + 1];
            const float wa0 = s_w20[n], wa1 = s_w20[n + 1];
            const float wb0 = s_w21[n], wb1 = s_w21[n + 1];
            #pragma unroll
            for (int i = 0; i < 4; ++i) {
                float h;
                h = acc[i][j][0] + bv0; h = h >= 0.f ? h : av0 * h;
                pr0[i*2]   = fmaf(h, wa0, pr0[i*2]);   pr1[i*2]   = fmaf(h, wb0, pr1[i*2]);
                h = acc[i][j][1] + bv1; h = h >= 0.f ? h : av1 * h;
                pr0[i*2]   = fmaf(h, wa1, pr0[i*2]);   pr1[i*2]   = fmaf(h, wb1, pr1[i*2]);
                h = acc[i][j][2] + bv0; h = h >= 0.f ? h : av0 * h;
                pr0[i*2+1] = fmaf(h, wa0, pr0[i*2+1]); pr1[i*2+1] = fmaf(h, wb0, pr1[i*2+1]);
                h = acc[i][j][3] + bv1; h = h >= 0.f ? h : av1 * h;
                pr0[i*2+1] = fmaf(h, wa1, pr0[i*2+1]); pr1[i*2+1] = fmaf(h, wb1, pr1[i*2+1]);
            }
        }
        #pragma unroll
        for (int i = 0; i < 8; ++i) {
            pr0[i] += __shfl_xor_sync(0xffffffffu, pr0[i], 1);
            pr0[i] += __shfl_xor_sync(0xffffffffu, pr0[i], 2);
            pr1[i] += __shfl_xor_sync(0xffffffffu, pr1[i], 1);
            pr1[i] += __shfl_xor_sync(0xffffffffu, pr1[i], 2);
        }
        if (qlane == 0) {
            #pragma unroll
            for (int i = 0; i < 4; ++i) {
                const int r0 = m_base + i * 16 + quad;
                s_part0[grp][warp_n][r0]     = pr0[i*2];
                s_part1[grp][warp_n][r0]     = pr1[i*2];
                s_part0[grp][warp_n][r0 + 8] = pr0[i*2+1];
                s_part1[grp][warp_n][r0 + 8] = pr1[i*2+1];
            }
        }
        GBAR(barid);

        // ---- per-edge log-softmax + NLL ----
        if (gtid < TILE_E) {
            const int e = t * TILE_E + gtid;
            if (e < E) {
                const float l0 = s_part0[grp][0][gtid] + s_part0[grp][1][gtid]
                               + s_part0[grp][2][gtid] + s_part0[grp][3][gtid] + bias0;
                const float l1 = s_part1[grp][0][gtid] + s_part1[grp][1][gtid]
                               + s_part1[grp][2][gtid] + s_part1[grp][3][gtid] + bias1;
                const int y   = s_y[grp][li & 3][gtid];
                const float mx  = fmaxf(l0, l1);
                const float lse = mx + log1pf(expf(-fabsf(l0 - l1)));
                dsum += (double)((y ? l1 : l0) - lse);
            }
        }
    }

    __syncthreads();   // both groups finished
    if (gtid < TILE_E) atomicAdd(&s_dsum, dsum);
    __syncthreads();
    if (tid == 0) atomicAdd(&g_loss_sum, s_dsum);
}

extern "C" void kernel_launch(void* const* d_in, const int* in_sizes, int n_in,
                              void* d_out, int out_size) {
    const float* feature = (const float*)d_in[0];
    const float* W1      = (const float*)d_in[1];
    const float* b1      = (const float*)d_in[2];
    const float* alpha   = (const float*)d_in[3];
    const float* W2      = (const float*)d_in[4];
    const float* b2      = (const float*)d_in[5];
    const int*   row     = (const int*)d_in[6];
    const int*   col     = (const int*)d_in[7];
    const int*   label   = (const int*)d_in[8];
    const int E  = in_sizes[6];
    const int nf = in_sizes[0];
    float* out = (float*)d_out;

    int sms = 148;
    cudaDeviceGetAttribute(&sms, cudaDevAttrMultiProcessorCount, 0);
    cudaFuncSetAttribute(hx_main_kernel,
                         cudaFuncAttributeMaxDynamicSharedMemorySize, DSMEM);

    hx_init_kernel<<<1, 1>>>();
    hx_prep_feat<<<(nf / 4 + 255) / 256, 256>>>(feature, nf / 4);
    hx_prep_w1<<<(KDIM * NHID) / 256, 256>>>(W1);

    const int ntiles = (E + TILE_E - 1) / TILE_E;
    hx_main_kernel<<<sms, THREADS, DSMEM>>>(b1, alpha, W2, b2, row, col, label, E, ntiles);
    hx_final_kernel<<<1, 1>>>(out, E);
}

// round 9
// speedup vs baseline: 1.5240x; 1.0199x over previous
#include <cuda_runtime.h>
#include <cuda_bf16.h>
#include <cstdint>

// Fused edge-MLP CE loss via warp-level bf16 mma.sync.
// R9: R8 + (a) one-time anti-phase stagger between the two 8-warp groups
// (named-barrier arrive/wait) so one group's GEMM overlaps the other's
// epilogue; (b) batched LDSMs per k-step; (c) float2-packed partials.

namespace {
constexpr int NHID    = 128;
constexpr int KDIM    = 256;
constexpr int TILE_E  = 128;
constexpr int THREADS = 512;
constexpr int A_BYTES = TILE_E * KDIM * 2;   // 64 KB per group A buffer
constexpr int B_BYTES = KDIM * NHID * 2;     // 64 KB W1 image
constexpr int DSMEM   = B_BYTES + 2 * A_BYTES + 256;
}

__device__ __align__(16) __nv_bfloat16 g_feat_bf16[(size_t)100000 * NHID];
__device__ __align__(16) __nv_bfloat16 g_w1_img[KDIM * NHID];
__device__ double g_loss_sum;

__device__ __forceinline__ uint32_t smem_u32(const void* p) {
    uint32_t a;
    asm("{ .reg .u64 t; cvta.to.shared.u64 t, %1; cvt.u32.u64 %0, t; }" : "=r"(a) : "l"(p));
    return a;
}

#define GBAR(id) asm volatile("bar.sync %0, 256;" :: "r"(id) : "memory")
#define GBAR_ARRIVE512(id) asm volatile("bar.arrive %0, 512;" :: "r"(id) : "memory")
#define GBAR_WAIT512(id)   asm volatile("bar.sync %0, 512;"   :: "r"(id) : "memory")

#define LDSM_X4(r, addr) \
    asm volatile("ldmatrix.sync.aligned.m8n8.x4.shared.b16 {%0,%1,%2,%3}, [%4];" \
        : "=r"((r)[0]), "=r"((r)[1]), "=r"((r)[2]), "=r"((r)[3]) : "r"(addr))
#define LDSM_X4T(r, addr) \
    asm volatile("ldmatrix.sync.aligned.m8n8.x4.trans.shared.b16 {%0,%1,%2,%3}, [%4];" \
        : "=r"((r)[0]), "=r"((r)[1]), "=r"((r)[2]), "=r"((r)[3]) : "r"(addr))

// ---------------- prep kernels ----------------
__global__ void hx_init_kernel() { g_loss_sum = 0.0; }

__global__ void hx_prep_feat(const float* __restrict__ f, int n4) {
    int i = blockIdx.x * blockDim.x + threadIdx.x;
    if (i < n4) {
        float4 v = reinterpret_cast<const float4*>(f)[i];
        __nv_bfloat162* dst = reinterpret_cast<__nv_bfloat162*>(g_feat_bf16);
        dst[i * 2]     = __floats2bfloat162_rn(v.x, v.y);
        dst[i * 2 + 1] = __floats2bfloat162_rn(v.z, v.w);
    }
}

__global__ void hx_prep_w1(const float* __restrict__ W1) {
    int idx = blockIdx.x * blockDim.x + threadIdx.x;   // 32768
    int k = idx >> 7, n = idx & 127;
    int c = n >> 3;
    int cs = (c & 8) | ((c & 7) ^ (k & 7));
    uint32_t off = (uint32_t)k * 256u + (uint32_t)cs * 16u + (uint32_t)(n & 7) * 2u;
    *reinterpret_cast<__nv_bfloat16*>(reinterpret_cast<char*>(g_w1_img) + off) =
        __float2bfloat16(W1[idx]);
}

__global__ void hx_final_kernel(float* out, int E) {
    out[0] = (float)(-g_loss_sum / (double)E);
}

// ---------------- device helpers ----------------
__device__ __forceinline__ void prefetch_tile(
    int tp, int E, const int* __restrict__ row, const int* __restrict__ col,
    const int* __restrict__ label, int gtid, int* __restrict__ s_nid,
    int* __restrict__ s_yrow)
{
    const int el = gtid >> 1, h = gtid & 1;
    int e = tp * TILE_E + el;
    if (e >= E) e = 0;
    const int r = row[e], c = col[e];
    s_nid[gtid] = h ? c : r;
    if (h == 0) s_yrow[el] = (label[r] == label[c]) ? 1 : 0;
}

__device__ __forceinline__ void gather_issue_warp(
    uint32_t Abuf, const int* __restrict__ s_nid, int wg, int lane)
{
    const int half = lane >> 4;
    const int i    = lane & 15;
    #pragma unroll
    for (int j = 0; j < 16; ++j) {
        const int rowidx = wg * 32 + j * 2 + half;
        const int el = rowidx >> 1, h = rowidx & 1;
        const int nid = s_nid[rowidx];
        const int c  = h * 16 + i;
        const int cs = (c & 24) | ((c & 7) ^ (el & 7));
        const char* src = reinterpret_cast<const char*>(g_feat_bf16)
                        + (size_t)nid * 256 + i * 16;
        asm volatile("cp.async.cg.shared.global [%0], [%1], 16;"
                     :: "r"(Abuf + (uint32_t)el * 512u + (uint32_t)cs * 16u),
                        "l"(src) : "memory");
    }
}

// ---------------- main persistent kernel ----------------
__global__ __launch_bounds__(THREADS, 1)
void hx_main_kernel(const float* __restrict__ b1,
                    const float* __restrict__ alpha,
                    const float* __restrict__ W2,
                    const float* __restrict__ b2,
                    const int* __restrict__ row,
                    const int* __restrict__ col,
                    const int* __restrict__ label,
                    int E, int ntiles)
{
    extern __shared__ char dyn[];
    __shared__ float s_b1[NHID], s_al[NHID], s_w20[NHID], s_w21[NHID];
    __shared__ float2 s_part[2][4][TILE_E];
    __shared__ int   s_nid[2][2][2 * TILE_E];
    __shared__ int   s_y[2][4][TILE_E];
    __shared__ double s_dsum;

    const int tid  = threadIdx.x;
    const int lane = tid & 31;
    const int warp = tid >> 5;
    const int grp  = warp >> 3;          // 0 or 1
    const int wg   = warp & 7;           // warp within group
    const int gtid = tid & 255;          // thread within group
    const int barid = 1 + grp;

    const uint32_t dynb = smem_u32(dyn);
    const uint32_t base = (dynb + 255u) & ~255u;
    const uint32_t Bsm  = base;
    const uint32_t Abuf = base + B_BYTES + (uint32_t)grp * A_BYTES;

    if (tid == 0) s_dsum = 0.0;
    if (tid < NHID) {
        s_b1[tid]  = b1[tid];
        s_al[tid]  = alpha[tid];
        s_w20[tid] = W2[2 * tid];
        s_w21[tid] = W2[2 * tid + 1];
    }
    {   // stage W1 image
        char* dst = dyn + (base - dynb);
        const int4* s = reinterpret_cast<const int4*>(g_w1_img);
        int4* d = reinterpret_cast<int4*>(dst);
        for (int i = tid; i < B_BYTES / 16; i += THREADS) d[i] = s[i];
    }

    const float bias0 = b2[0], bias1 = b2[1];

    // warp tile m64 x n32: group grid 2m x 4n
    const int warp_m = wg & 1, warp_n = wg >> 1;
    const int m_base = warp_m * 64, n_base = warp_n * 32;

    uint32_t rowA[4];
    #pragma unroll
    for (int i = 0; i < 4; ++i)
        rowA[i] = (uint32_t)(m_base + i * 16 + (lane & 15)) * 512u;
    const int xA  = lane & 7;
    const int csA = lane >> 4;

    uint32_t bBase[2];
    {
        const int kr = lane & 15;
        const int xB = lane & 7;
        #pragma unroll
        for (int j2 = 0; j2 < 2; ++j2) {
            const int cn = warp_n * 4 + j2 * 2 + (lane >> 4);
            const int cs = (cn & 8) | ((cn & 7) ^ xB);
            bBase[j2] = Bsm + (uint32_t)kr * 256u + (uint32_t)cs * 16u;
        }
    }

    const int stride = 2 * gridDim.x;
    const int t0 = 2 * blockIdx.x + grp;
    const bool grp1_active = (2 * blockIdx.x + 1) < ntiles;  // group 1 has tiles
    double dsum = 0.0;

    __syncthreads();   // B image + params ready (last block-wide barrier)

    // ---- per-group warm-up ----
    if (t0 < ntiles) {
        prefetch_tile(t0, E, row, col, label, gtid, s_nid[grp][0], s_y[grp][0]);
        GBAR(barid);
        gather_issue_warp(Abuf, s_nid[grp][0], wg, lane);
        asm volatile("cp.async.commit_group;" ::: "memory");
        if (t0 + stride < ntiles)
            prefetch_tile(t0 + stride, E, row, col, label, gtid,
                          s_nid[grp][1], s_y[grp][1]);
    }

    // ---- anti-phase stagger: group 1 waits for group 0's first GEMM ----
    if (grp == 1 && t0 < ntiles) GBAR_WAIT512(3);

    int li = 0;
    for (int t = t0; t < ntiles; t += stride, ++li) {
        asm volatile("cp.async.wait_group 0;" ::: "memory");
        GBAR(barid);

        if (t + 2 * stride < ntiles)
            prefetch_tile(t + 2 * stride, E, row, col, label, gtid,
                          s_nid[grp][li & 1], s_y[grp][(li + 2) & 3]);

        // ---- GEMM: 16 k-steps, warp tile m64n32, batched LDSMs ----
        float acc[4][4][4];
        #pragma unroll
        for (int i = 0; i < 4; ++i)
            #pragma unroll
            for (int j = 0; j < 4; ++j) {
                acc[i][j][0] = 0.f; acc[i][j][1] = 0.f;
                acc[i][j][2] = 0.f; acc[i][j][3] = 0.f;
            }

        #pragma unroll
        for (int ks = 0; ks < 16; ++ks) {
            uint32_t b[2][4], a[4][4];
            #pragma unroll
            for (int j2 = 0; j2 < 2; ++j2)
                LDSM_X4T(b[j2], bBase[j2] + (uint32_t)ks * 4096u);
            const int c  = 2 * ks + csA;
            const int cs = (c & 24) | ((c & 7) ^ xA);
            #pragma unroll
            for (int i = 0; i < 4; ++i)
                LDSM_X4(a[i], Abuf + rowA[i] + (uint32_t)cs * 16u);
            #pragma unroll
            for (int i = 0; i < 4; ++i)
                #pragma unroll
                for (int j = 0; j < 4; ++j) {
                    const uint32_t bb0 = b[j >> 1][(j & 1) * 2];
                    const uint32_t bb1 = b[j >> 1][(j & 1) * 2 + 1];
                    asm volatile(
                        "mma.sync.aligned.m16n8k16.row.col.f32.bf16.bf16.f32 "
                        "{%0,%1,%2,%3}, {%4,%5,%6,%7}, {%8,%9}, {%0,%1,%2,%3};"
                        : "+f"(acc[i][j][0]), "+f"(acc[i][j][1]),
                          "+f"(acc[i][j][2]), "+f"(acc[i][j][3])
                        : "r"(a[i][0]), "r"(a[i][1]), "r"(a[i][2]), "r"(a[i][3]),
                          "r"(bb0), "r"(bb1));
                }
        }

        GBAR(barid);   // group done reading Abuf

        // group 0 signals its first GEMM is done -> releases group 1
        if (grp == 0 && li == 0 && grp1_active) GBAR_ARRIVE512(3);

        // ---- gather next tile immediately ----
        const int tn = t + stride;
        if (tn < ntiles) {
            gather_issue_warp(Abuf, s_nid[grp][(li + 1) & 1], wg, lane);
            asm volatile("cp.async.commit_group;" ::: "memory");
        }

        // ---- fragment epilogue: PReLU + 128->2 projection ----
        const int quad = lane >> 2, qlane = lane & 3;
        float pr0[8], pr1[8];
        #pragma unroll
        for (int i = 0; i < 8; ++i) { pr0[i] = 0.f; pr1[i] = 0.f; }

        #pragma unroll
        for (int j = 0; j < 4; ++j) {
            const int n = n_base + j * 8 + qlane * 2;
            const float bv0 = s_b1[n],  bv1 = s_b1[n + 1];
            const float av0 = s_al[n],  av1 = s_al[n + 1];
            const float wa0 = s_w20[n], wa1 = s_w20[n + 1];
            const float wb0 = s_w21[n], wb1 = s_w21[n + 1];
            #pragma unroll
            for (int i = 0; i < 4; ++i) {
                float h;
                h = acc[i][j][0] + bv0; h = h >= 0.f ? h : av0 * h;
                pr0[i*2]   = fmaf(h, wa0, pr0[i*2]);   pr1[i*2]   = fmaf(h, wb0, pr1[i*2]);
                h = acc[i][j][1] + bv1; h = h >= 0.f ? h : av1 * h;
                pr0[i*2]   = fmaf(h, wa1, pr0[i*2]);   pr1[i*2]   = fmaf(h, wb1, pr1[i*2]);
                h = acc[i][j][2] + bv0; h = h >= 0.f ? h : av0 * h;
                pr0[i*2+1] = fmaf(h, wa0, pr0[i*2+1]); pr1[i*2+1] = fmaf(h, wb0, pr1[i*2+1]);
                h = acc[i][j][3] + bv1; h = h >= 0.f ? h : av1 * h;
                pr0[i*2+1] = fmaf(h, wa1, pr0[i*2+1]); pr1[i*2+1] = fmaf(h, wb1, pr1[i*2+1]);
            }
        }
        #pragma unroll
        for (int i = 0; i < 8; ++i) {
            pr0[i] += __shfl_xor_sync(0xffffffffu, pr0[i], 1);
            pr0[i] += __shfl_xor_sync(0xffffffffu, pr0[i], 2);
            pr1[i] += __shfl_xor_sync(0xffffffffu, pr1[i], 1);
            pr1[i] += __shfl_xor_sync(0xffffffffu, pr1[i], 2);
        }
        if (qlane == 0) {
            #pragma unroll
            for (int i = 0; i < 4; ++i) {
                const int r0 = m_base + i * 16 + quad;
                s_part[grp][warp_n][r0]     = make_float2(pr0[i*2],   pr1[i*2]);
                s_part[grp][warp_n][r0 + 8] = make_float2(pr0[i*2+1], pr1[i*2+1]);
            }
        }
        GBAR(barid);

        // ---- per-edge log-softmax + NLL ----
        if (gtid < TILE_E) {
            const int e = t * TILE_E + gtid;
            if (e < E) {
                const float2 q0 = s_part[grp][0][gtid];
                const float2 q1 = s_part[grp][1][gtid];
                const float2 q2 = s_part[grp][2][gtid];
                const float2 q3 = s_part[grp][3][gtid];
                const float l0 = q0.x + q1.x + q2.x + q3.x + bias0;
                const float l1 = q0.y + q1.y + q2.y + q3.y + bias1;
                const int y   = s_y[grp][li & 3][gtid];
                const float mx  = fmaxf(l0, l1);
                const float lse = mx + log1pf(expf(-fabsf(l0 - l1)));
                dsum += (double)((y ? l1 : l0) - lse);
            }
        }
    }

    __syncthreads();   // both groups finished
    if (gtid < TILE_E) atomicAdd(&s_dsum, dsum);
    __syncthreads();
    if (tid == 0) atomicAdd(&g_loss_sum, s_dsum);
}

extern "C" void kernel_launch(void* const* d_in, const int* in_sizes, int n_in,
                              void* d_out, int out_size) {
    const float* feature = (const float*)d_in[0];
    const float* W1      = (const float*)d_in[1];
    const float* b1      = (const float*)d_in[2];
    const float* alpha   = (const float*)d_in[3];
    const float* W2      = (const float*)d_in[4];
    const float* b2      = (const float*)d_in[5];
    const int*   row     = (const int*)d_in[6];
    const int*   col     = (const int*)d_in[7];
    const int*   label   = (const int*)d_in[8];
    const int E  = in_sizes[6];
    const int nf = in_sizes[0];
    float* out = (float*)d_out;

    int sms = 148;
    cudaDeviceGetAttribute(&sms, cudaDevAttrMultiProcessorCount, 0);
    cudaFuncSetAttribute(hx_main_kernel,
                         cudaFuncAttributeMaxDynamicSharedMemorySize, DSMEM);

    hx_init_kernel<<<1, 1>>>();
    hx_prep_feat<<<(nf / 4 + 255) / 256, 256>>>(feature, nf / 4);
    hx_prep_w1<<<(KDIM * NHID) / 256, 256>>>(W1);

    const int ntiles = (E + TILE_E - 1) / TILE_E;
    hx_main_kernel<<<sms, THREADS, DSMEM>>>(b1, alpha, W2, b2, row, col, label, E, ntiles);
    hx_final_kernel<<<1, 1>>>(out, E);
}